// round 12
// baseline (speedup 1.0000x reference)
#include <cuda_runtime.h>
#include <stdint.h>

// Lukasiewicz t-norm feature expansion, compile-time-unrolled.
//   out[:, 0:16)    = x
//   out[:, 16:136)  = max(x[i]+x[j] - 1, 0)       i<j    (120)
//   out[:, 136:696) = max(x[i]+x[j]+x[k] - 2, 0)  i<j<k  (560)
// N = 131072 rows, 696 out cols (= 174 float4). Store-BW bound.
//
// R4 structure (proven minimal DRAM traffic: 16-float4 chunks, 2-row x 256B
// copy-out pieces) + occupancy raise: no xm1/xm2 arrays and
// __launch_bounds__(128,8) -> 64 regs -> 6 blocks/SM (24 warps) vs R4's 5.

#define N_ROWS   131072
#define OUT_V4   174
#define CH_V4    16            // float4 columns per chunk
#define NCHUNK   11            // 10 full chunks + 1 overlapped tail (base 158)
#define WARPS_PB 4
#define BLOCK_T  (WARPS_PB * 32)

struct TabT {
    unsigned char k[696], a[696], b[696], c[696];
};

__host__ __device__ constexpr TabT make_tab() {
    TabT t{};
    int n = 0;
    for (int i = 0; i < 16; ++i) {
        t.k[n] = 1; t.a[n] = (unsigned char)i; t.b[n] = 0; t.c[n] = 0; ++n;
    }
    for (int i = 0; i < 16; ++i)
        for (int j = i + 1; j < 16; ++j) {
            t.k[n] = 2; t.a[n] = (unsigned char)i; t.b[n] = (unsigned char)j;
            t.c[n] = 0; ++n;
        }
    for (int i = 0; i < 16; ++i)
        for (int j = i + 1; j < 16; ++j)
            for (int l = j + 1; l < 16; ++l) {
                t.k[n] = 3; t.a[n] = (unsigned char)i; t.b[n] = (unsigned char)j;
                t.c[n] = (unsigned char)l; ++n;
            }
    return t;
}
__device__ constexpr TabT TAB = make_tab();

__global__ void __launch_bounds__(BLOCK_T, 8)
luk_kernel(const float4* __restrict__ x4, float4* __restrict__ out4)
{
    const int tid  = threadIdx.x;
    const int warp = tid >> 5;
    const int lane = tid & 31;

    const long long tileRow = ((long long)blockIdx.x * WARPS_PB + warp) * 32;
    const long long myRow   = tileRow + lane;

    // Load this lane's row (16 floats) into registers.
    float xv[16];
    {
        const float4 v0 = x4[myRow * 4 + 0];
        const float4 v1 = x4[myRow * 4 + 1];
        const float4 v2 = x4[myRow * 4 + 2];
        const float4 v3 = x4[myRow * 4 + 3];
        xv[0]=v0.x;  xv[1]=v0.y;  xv[2]=v0.z;  xv[3]=v0.w;
        xv[4]=v1.x;  xv[5]=v1.y;  xv[6]=v1.z;  xv[7]=v1.w;
        xv[8]=v2.x;  xv[9]=v2.y;  xv[10]=v2.z; xv[11]=v2.w;
        xv[12]=v3.x; xv[13]=v3.y; xv[14]=v3.z; xv[15]=v3.w;
    }

    // Per-warp staging buffer: [32 rows][17 float4] (stride 68 floats ->
    // bank-conflict-free for both the compute-phase STS.128 and copy-out LDS.128)
    __shared__ float4 sh[WARPS_PB][32][CH_V4 + 1];
    float4* __restrict__ mysh = &sh[warp][lane][0];

    // Per-lane output base pointer for the copy-out phase (immediate offsets).
    float4* __restrict__ opBase =
        out4 + (tileRow + (lane >> 4)) * OUT_V4 + (lane & 15);

#pragma unroll
    for (int ch = 0; ch < NCHUNK; ++ch) {
        const int baseV4 = (ch == NCHUNK - 1) ? (OUT_V4 - CH_V4) : ch * CH_V4;
        const int base   = baseV4 * 4;

        // ---- compute phase: this lane's row, 64 columns, all-register ----
#pragma unroll
        for (int v = 0; v < CH_V4; ++v) {
            float r[4];
#pragma unroll
            for (int e = 0; e < 4; ++e) {
                const int col = base + v * 4 + e;
                const int K = TAB.k[col];
                const int A = TAB.a[col];
                const int B = TAB.b[col];
                const int C = TAB.c[col];
                if (K == 1)      r[e] = xv[A];
                else if (K == 2) r[e] = fmaxf(xv[A] + xv[B] - 1.0f, 0.0f);
                else             r[e] = fmaxf(xv[A] + (xv[B] + xv[C]) - 2.0f, 0.0f);
            }
            mysh[v] = make_float4(r[0], r[1], r[2], r[3]);
        }
        __syncwarp();

        // ---- copy-out phase: half-warp per row, coalesced 256B pieces ----
#pragma unroll
        for (int t = 0; t < 16; ++t) {
            const int rr = t * 2 + (lane >> 4);
            const float4 val = sh[warp][rr][lane & 15];
            opBase[(long long)t * (2 * OUT_V4) + baseV4] = val;
        }
        __syncwarp();
    }
}

extern "C" void kernel_launch(void* const* d_in, const int* in_sizes, int n_in,
                              void* d_out, int out_size)
{
    const float4* x4 = (const float4*)d_in[0];
    float4* out4 = (float4*)d_out;
    (void)in_sizes; (void)n_in; (void)out_size;

    const int grid = N_ROWS / (WARPS_PB * 32);   // 1024 blocks
    luk_kernel<<<grid, BLOCK_T>>>(x4, out4);
}

// round 16
// speedup vs baseline: 1.4528x; 1.4528x over previous
#include <cuda_runtime.h>
#include <stdint.h>

// Lukasiewicz t-norm feature expansion — smem tile + single TMA bulk store.
//   out[:, 0:16)    = x
//   out[:, 16:136)  = max(x[i]+x[j] - 1, 0)       i<j    (120)
//   out[:, 136:696) = max(x[i]+x[j]+x[k] - 2, 0)  i<j<k  (560)
// N = 131072 rows, 696 out cols (174 float4). Store-BW bound.
//
// Block = 128 threads = 32 consecutive rows. Each warp computes a quarter of
// the 174 float4 columns for ALL 32 rows (lane = row, x in registers, all
// combination indices compile-time constants). Tile staged CONTIGUOUS in
// dynamic shared (32 x 174 float4 = 89,088 B, exactly 696 cache lines,
// 128B-aligned span per block), then written with ONE cp.async.bulk
// smem->global: full-line TMA bursts, zero STG issue, no LDS->STG register
// chains (R12 showed reg-starved LDS/STG batching is the failure mode).

#define N_ROWS    131072
#define ROWS_PB   32
#define OUT_V4    174
#define TILE_V4   (ROWS_PB * OUT_V4)        // 5568 float4
#define TILE_BYTES (TILE_V4 * 16)           // 89,088 B
#define BLOCK_T   128

struct TabT {
    unsigned char k[696], a[696], b[696], c[696];
};

__host__ __device__ constexpr TabT make_tab() {
    TabT t{};
    int n = 0;
    for (int i = 0; i < 16; ++i) {
        t.k[n] = 1; t.a[n] = (unsigned char)i; t.b[n] = 0; t.c[n] = 0; ++n;
    }
    for (int i = 0; i < 16; ++i)
        for (int j = i + 1; j < 16; ++j) {
            t.k[n] = 2; t.a[n] = (unsigned char)i; t.b[n] = (unsigned char)j;
            t.c[n] = 0; ++n;
        }
    for (int i = 0; i < 16; ++i)
        for (int j = i + 1; j < 16; ++j)
            for (int l = j + 1; l < 16; ++l) {
                t.k[n] = 3; t.a[n] = (unsigned char)i; t.b[n] = (unsigned char)j;
                t.c[n] = (unsigned char)l; ++n;
            }
    return t;
}
__device__ constexpr TabT TAB = make_tab();

// Compute float4 columns [LO, HI) of this lane's row into shared.
template <int LO, int HI>
__device__ __forceinline__ void compute_cols(const float xv[16],
                                             float4* __restrict__ shrow)
{
#pragma unroll
    for (int v4 = LO; v4 < HI; ++v4) {
        float r[4];
#pragma unroll
        for (int e = 0; e < 4; ++e) {
            const int col = v4 * 4 + e;
            const int K = TAB.k[col];
            const int A = TAB.a[col];
            const int B = TAB.b[col];
            const int C = TAB.c[col];
            if (K == 1)      r[e] = xv[A];
            else if (K == 2) r[e] = fmaxf(xv[A] + xv[B] - 1.0f, 0.0f);
            else             r[e] = fmaxf(xv[A] + (xv[B] + xv[C]) - 2.0f, 0.0f);
        }
        shrow[v4] = make_float4(r[0], r[1], r[2], r[3]);
    }
}

__global__ void __launch_bounds__(BLOCK_T)
luk_kernel(const float4* __restrict__ x4, float4* __restrict__ out4)
{
    extern __shared__ float4 sh[];   // [ROWS_PB][OUT_V4], contiguous

    const int tid  = threadIdx.x;
    const int warp = tid >> 5;
    const int lane = tid & 31;

    const long long tileRow = (long long)blockIdx.x * ROWS_PB;
    const long long myRow   = tileRow + lane;

    // Load this lane's row (16 floats) into registers (same rows in all
    // 4 warps; redundant loads hit L1/L2).
    float xv[16];
    {
        const float4 v0 = x4[myRow * 4 + 0];
        const float4 v1 = x4[myRow * 4 + 1];
        const float4 v2 = x4[myRow * 4 + 2];
        const float4 v3 = x4[myRow * 4 + 3];
        xv[0]=v0.x;  xv[1]=v0.y;  xv[2]=v0.z;  xv[3]=v0.w;
        xv[4]=v1.x;  xv[5]=v1.y;  xv[6]=v1.z;  xv[7]=v1.w;
        xv[8]=v2.x;  xv[9]=v2.y;  xv[10]=v2.z; xv[11]=v2.w;
        xv[12]=v3.x; xv[13]=v3.y; xv[14]=v3.z; xv[15]=v3.w;
    }

    // Compute phase: lane = row; each warp owns a column range.
    // (Unpadded stride 174 f4 -> 2-way STS bank conflict; compute is <10%
    // of the kernel, irrelevant.)
    float4* __restrict__ shrow = sh + lane * OUT_V4;
    if      (warp == 0) compute_cols<0,   44>(xv, shrow);
    else if (warp == 1) compute_cols<44,  88>(xv, shrow);
    else if (warp == 2) compute_cols<88, 132>(xv, shrow);
    else                compute_cols<132,174>(xv, shrow);

    __syncthreads();

    // Single TMA bulk store of the whole tile (89,088B, 128B-aligned span).
    if (tid == 0) {
        asm volatile("fence.proxy.async.shared::cta;" ::: "memory");
        uint32_t saddr;
        asm("{ .reg .u64 t; cvta.to.shared.u64 t, %1; cvt.u32.u64 %0, t; }"
            : "=r"(saddr) : "l"(sh));
        const float4* gdst = out4 + (long long)blockIdx.x * TILE_V4;
        asm volatile(
            "cp.async.bulk.global.shared::cta.bulk_group [%0], [%1], %2;"
            :: "l"(gdst), "r"(saddr), "r"((unsigned)TILE_BYTES) : "memory");
        asm volatile("cp.async.bulk.commit_group;" ::: "memory");
        asm volatile("cp.async.bulk.wait_group 0;" ::: "memory");
    }
}

extern "C" void kernel_launch(void* const* d_in, const int* in_sizes, int n_in,
                              void* d_out, int out_size)
{
    const float4* x4 = (const float4*)d_in[0];
    float4* out4 = (float4*)d_out;
    (void)in_sizes; (void)n_in; (void)out_size;

    cudaFuncSetAttribute(luk_kernel,
                         cudaFuncAttributeMaxDynamicSharedMemorySize,
                         TILE_BYTES);

    const int grid = N_ROWS / ROWS_PB;   // 4096 blocks
    luk_kernel<<<grid, BLOCK_T, TILE_BYTES>>>(x4, out4);
}